// round 3
// baseline (speedup 1.0000x reference)
#include <cuda_runtime.h>
#include <math.h>

#define Hh 160
#define Ww 160
#define HWp 25600
#define Cc 64
#define OUTC 64
#define Bb 4

// scratch: precomputed sample coords + mask, [B][9][H*W]
__device__ float g_py[Bb * 9 * HWp];
__device__ float g_px[Bb * 9 * HWp];
__device__ float g_m [Bb * 9 * HWp];

__device__ __forceinline__ unsigned long long pk2(float lo, float hi) {
    unsigned long long r;
    asm("mov.b64 %0,{%1,%2};" : "=l"(r) : "f"(lo), "f"(hi));
    return r;
}
__device__ __forceinline__ void upk2(unsigned long long v, float& lo, float& hi) {
    asm("mov.b64 {%0,%1},%2;" : "=f"(lo), "=f"(hi) : "l"(v));
}
__device__ __forceinline__ void fma2(unsigned long long& d, unsigned long long a, unsigned long long b) {
    asm("fma.rn.f32x2 %0,%1,%2,%0;" : "+l"(d) : "l"(a), "l"(b));
}

// ============================================================================
// Kernel 1: offset(18ch) + mask(9ch) 3x3 conv, one thread per pixel.
// 28 output channels (27 + 1 zero pad) as 14 f32x2 accumulators.
// Weights in shared, transposed to [c][tap][o] so the o-dim is contiguous
// (f32x2-pair friendly, broadcast LDS across the warp).
// ============================================================================
__global__ void __launch_bounds__(256) omconv_kernel(
    const float* __restrict__ x,
    const float* __restrict__ ow, const float* __restrict__ ob,
    const float* __restrict__ mw, const float* __restrict__ mb)
{
    extern __shared__ float Wsh[];  // [64][9][28] = 16128 floats
    const int tid = threadIdx.x;

    for (int idx = tid; idx < 64 * 9 * 28; idx += 256) {
        int o = idx % 28;
        int ck = idx / 28;
        int t = ck % 9;
        int c = ck / 9;
        float w;
        if (o < 18)      w = ow[(o * 64 + c) * 9 + t];
        else if (o < 27) w = mw[((o - 18) * 64 + c) * 9 + t];
        else             w = 0.f;
        Wsh[idx] = w;
    }
    __syncthreads();

    const int pid = blockIdx.x * 256 + tid;     // 400*256 = 102400 exactly
    const int b = pid / HWp;
    const int p = pid - b * HWp;
    const int i = p / Ww;
    const int j = p - i * Ww;

    unsigned long long acc[14];
#pragma unroll
    for (int u = 0; u < 14; u++) {
        int o0 = 2 * u, o1 = 2 * u + 1;
        float blo = (o0 < 18) ? ob[o0] : mb[o0 - 18];
        float bhi = (o1 < 18) ? ob[o1] : ((o1 < 27) ? mb[o1 - 18] : 0.f);
        acc[u] = pk2(blo, bhi);
    }

    int  ioff[9];
    bool vld[9];
#pragma unroll
    for (int t = 0; t < 9; t++) {
        int yy = i + t / 3 - 1;
        int xx = j + t % 3 - 1;
        vld[t] = (yy >= 0) && (yy < Hh) && (xx >= 0) && (xx < Ww);
        int yc = min(max(yy, 0), Hh - 1);
        int xc = min(max(xx, 0), Ww - 1);
        ioff[t] = yc * Ww + xc;
    }

    const float* xb = x + (size_t)b * Cc * HWp;
    const unsigned long long* Wu = (const unsigned long long*)Wsh;

    for (int c = 0; c < 64; c++) {
        const float* xc = xb + c * HWp;
        float v[9];
#pragma unroll
        for (int t = 0; t < 9; t++) v[t] = vld[t] ? __ldg(xc + ioff[t]) : 0.f;
#pragma unroll
        for (int t = 0; t < 9; t++) {
            unsigned long long vv = pk2(v[t], v[t]);
            const unsigned long long* wr = Wu + (c * 9 + t) * 14;
#pragma unroll
            for (int u = 0; u < 14; u++) fma2(acc[u], wr[u], vv);
        }
    }

    float accf[28];
#pragma unroll
    for (int u = 0; u < 14; u++) upk2(acc[u], accf[2 * u], accf[2 * u + 1]);

#pragma unroll
    for (int k = 0; k < 9; k++) {
        float offy = accf[2 * k];
        float offx = accf[2 * k + 1];
        float m = 1.f / (1.f + expf(-accf[18 + k]));
        float py = offy + (float)(i - 1 + k / 3);
        float px = offx + (float)(j - 1 + k % 3);
        int o = (b * 9 + k) * HWp + p;
        g_py[o] = py;
        g_px[o] = px;
        g_m[o]  = m;
    }
}

// ============================================================================
// Kernel 2: per 128-pixel tile: for each tap k, sample masked bilinear tile
// S[64][128] into smem, then GEMM-accumulate out[64][128] += Wk[64][64] * S.
// 256 threads = 16x16; each thread owns 4 outch x 8 pixels as f32x2 pairs.
// ============================================================================
__global__ void __launch_bounds__(256) dcn_kernel(
    const float* __restrict__ x,
    const float* __restrict__ dw,
    float* __restrict__ out)
{
    extern __shared__ float sm[];
    float* Ws = sm;           // [64 c][64 o] = 4096 floats
    float* S  = sm + 4096;    // [64 c][128 pix] = 8192 floats

    const int tid = threadIdx.x;
    const int b = blockIdx.x / 200;                // 200 tiles per image
    const int pbase = (blockIdx.x % 200) * 128;    // in-image pixel base
    const int tx = tid & 15;
    const int ty = tid >> 4;

    const int pix = tid & 127;                     // sampling role
    const int cg  = tid >> 7;                      // channel half (0/1)
    const float* xb = x + (size_t)(b * 64 + cg * 32) * HWp;

    unsigned long long acc[4][4];
#pragma unroll
    for (int oi = 0; oi < 4; oi++)
#pragma unroll
        for (int pp = 0; pp < 4; pp++) acc[oi][pp] = 0ull;

    for (int k = 0; k < 9; k++) {
        __syncthreads();  // protect Ws/S from previous GEMM readers

        // --- stage Wk: Ws[c*64+o] = dcn_w[o][c][k] ---
#pragma unroll
        for (int r = 0; r < 16; r++) {
            int idx = tid + r * 256;               // 0..4095
            int c = idx >> 6;
            int o = idx & 63;
            Ws[idx] = __ldg(dw + (o * 64 + c) * 9 + k);
        }

        // --- sampling: S[c][pix] = mask * bilinear(x, py, px) ---
        {
            int gi = (b * 9 + k) * HWp + pbase + pix;
            float py = g_py[gi], px = g_px[gi], m = g_m[gi];
            float y0f = floorf(py), x0f = floorf(px);
            int y0 = (int)y0f, x0 = (int)x0f;
            float wy1 = py - y0f, wx1 = px - x0f;
            float wy0 = 1.f - wy1, wx0 = 1.f - wx1;
            bool yv0 = (y0 >= 0) && (y0 < Hh);
            bool yv1 = (y0 + 1 >= 0) && (y0 + 1 < Hh);
            bool xv0 = (x0 >= 0) && (x0 < Ww);
            bool xv1 = (x0 + 1 >= 0) && (x0 + 1 < Ww);
            float w00 = (yv0 && xv0) ? wy0 * wx0 * m : 0.f;
            float w01 = (yv0 && xv1) ? wy0 * wx1 * m : 0.f;
            float w10 = (yv1 && xv0) ? wy1 * wx0 * m : 0.f;
            float w11 = (yv1 && xv1) ? wy1 * wx1 * m : 0.f;
            int y0c = min(max(y0, 0), Hh - 1);
            int y1c = min(max(y0 + 1, 0), Hh - 1);
            int x0c = min(max(x0, 0), Ww - 1);
            int x1c = min(max(x0 + 1, 0), Ww - 1);
            int i00 = y0c * Ww + x0c, i01 = y0c * Ww + x1c;
            int i10 = y1c * Ww + x0c, i11 = y1c * Ww + x1c;
#pragma unroll 4
            for (int c = 0; c < 32; c++) {
                const float* xc = xb + c * HWp;
                float s = w00 * __ldg(xc + i00) + w01 * __ldg(xc + i01)
                        + w10 * __ldg(xc + i10) + w11 * __ldg(xc + i11);
                S[(cg * 32 + c) * 128 + pix] = s;
            }
        }
        __syncthreads();

        // --- GEMM: acc[4o][8pix] += Wk^T * S ---
        {
            const float4*     Ws4 = (const float4*)Ws;
            const ulonglong2* Su2 = (const ulonglong2*)S;
#pragma unroll 8
            for (int cc = 0; cc < 64; cc++) {
                float4 av = Ws4[cc * 16 + ty];
                ulonglong2 b0 = Su2[cc * 32 + tx * 2];
                ulonglong2 b1 = Su2[cc * 32 + tx * 2 + 1];
                unsigned long long a0 = pk2(av.x, av.x);
                unsigned long long a1 = pk2(av.y, av.y);
                unsigned long long a2 = pk2(av.z, av.z);
                unsigned long long a3 = pk2(av.w, av.w);
                fma2(acc[0][0], a0, b0.x); fma2(acc[0][1], a0, b0.y);
                fma2(acc[0][2], a0, b1.x); fma2(acc[0][3], a0, b1.y);
                fma2(acc[1][0], a1, b0.x); fma2(acc[1][1], a1, b0.y);
                fma2(acc[1][2], a1, b1.x); fma2(acc[1][3], a1, b1.y);
                fma2(acc[2][0], a2, b0.x); fma2(acc[2][1], a2, b0.y);
                fma2(acc[2][2], a2, b1.x); fma2(acc[2][3], a2, b1.y);
                fma2(acc[3][0], a3, b0.x); fma2(acc[3][1], a3, b0.y);
                fma2(acc[3][2], a3, b1.x); fma2(acc[3][3], a3, b1.y);
            }
        }
    }

    // --- epilogue: out[b][o][pbase + tx*8 .. +7] ---
    const int p0 = pbase + tx * 8;
    float* obp = out + (size_t)(b * 64 + ty * 4) * HWp + p0;
#pragma unroll
    for (int oi = 0; oi < 4; oi++) {
        float4 v0, v1;
        upk2(acc[oi][0], v0.x, v0.y);
        upk2(acc[oi][1], v0.z, v0.w);
        upk2(acc[oi][2], v1.x, v1.y);
        upk2(acc[oi][3], v1.z, v1.w);
        *(float4*)(obp + (size_t)oi * HWp)     = v0;
        *(float4*)(obp + (size_t)oi * HWp + 4) = v1;
    }
}

extern "C" void kernel_launch(void* const* d_in, const int* in_sizes, int n_in,
                              void* d_out, int out_size)
{
    const float* x        = (const float*)d_in[0];
    const float* offset_w = (const float*)d_in[1];
    const float* offset_b = (const float*)d_in[2];
    const float* mask_w   = (const float*)d_in[3];
    const float* mask_b   = (const float*)d_in[4];
    const float* dcn_w    = (const float*)d_in[5];
    float* out = (float*)d_out;

    const int smem1 = 64 * 9 * 28 * 4;   // 64512 B
    const int smem2 = (4096 + 8192) * 4; // 49152 B
    cudaFuncSetAttribute(omconv_kernel, cudaFuncAttributeMaxDynamicSharedMemorySize, smem1);
    cudaFuncSetAttribute(dcn_kernel,    cudaFuncAttributeMaxDynamicSharedMemorySize, smem2);

    omconv_kernel<<<400, 256, smem1>>>(x, offset_w, offset_b, mask_w, mask_b);
    dcn_kernel<<<800, 256, smem2>>>(x, dcn_w, out);
}

// round 4
// speedup vs baseline: 1.2076x; 1.2076x over previous
#include <cuda_runtime.h>
#include <math.h>

#define Hh 160
#define Ww 160
#define HWp 25600
#define Cc 64
#define OUTC 64
#define Bb 4

// scratch: precomputed sample coords + mask, [B][9][H*W]
__device__ float g_py[Bb * 9 * HWp];
__device__ float g_px[Bb * 9 * HWp];
__device__ float g_m [Bb * 9 * HWp];

__device__ __forceinline__ unsigned long long pk2(float lo, float hi) {
    unsigned long long r;
    asm("mov.b64 %0,{%1,%2};" : "=l"(r) : "f"(lo), "f"(hi));
    return r;
}
__device__ __forceinline__ void upk2(unsigned long long v, float& lo, float& hi) {
    asm("mov.b64 {%0,%1},%2;" : "=f"(lo), "=f"(hi) : "l"(v));
}
__device__ __forceinline__ void fma2(unsigned long long& d, unsigned long long a, unsigned long long b) {
    asm("fma.rn.f32x2 %0,%1,%2,%0;" : "+l"(d) : "l"(a), "l"(b));
}

// ============================================================================
// Kernel 1: offset(18ch) + mask(9ch) 3x3 conv, one thread per pixel.
// 28 output channels (27 + 1 zero pad) as 14 f32x2 accumulators.
// Weights in shared, transposed to [c][tap][o]; read as LDS.128 (2 f32x2 per
// load) to halve LDS issue pressure.
// ============================================================================
__global__ void __launch_bounds__(256) omconv_kernel(
    const float* __restrict__ x,
    const float* __restrict__ ow, const float* __restrict__ ob,
    const float* __restrict__ mw, const float* __restrict__ mb)
{
    extern __shared__ float Wsh[];  // [64][9][28] = 16128 floats (row = 112B = 7x16B)
    const int tid = threadIdx.x;

    for (int idx = tid; idx < 64 * 9 * 28; idx += 256) {
        int o = idx % 28;
        int ck = idx / 28;
        int t = ck % 9;
        int c = ck / 9;
        float w;
        if (o < 18)      w = ow[(o * 64 + c) * 9 + t];
        else if (o < 27) w = mw[((o - 18) * 64 + c) * 9 + t];
        else             w = 0.f;
        Wsh[idx] = w;
    }
    __syncthreads();

    const int pid = blockIdx.x * 256 + tid;     // 400*256 = 102400 exactly
    const int b = pid / HWp;
    const int p = pid - b * HWp;
    const int i = p / Ww;
    const int j = p - i * Ww;

    unsigned long long acc[14];
#pragma unroll
    for (int u = 0; u < 14; u++) {
        int o0 = 2 * u, o1 = 2 * u + 1;
        float blo = (o0 < 18) ? ob[o0] : mb[o0 - 18];
        float bhi = (o1 < 18) ? ob[o1] : ((o1 < 27) ? mb[o1 - 18] : 0.f);
        acc[u] = pk2(blo, bhi);
    }

    int  ioff[9];
    bool vld[9];
#pragma unroll
    for (int t = 0; t < 9; t++) {
        int yy = i + t / 3 - 1;
        int xx = j + t % 3 - 1;
        vld[t] = (yy >= 0) && (yy < Hh) && (xx >= 0) && (xx < Ww);
        int yc = min(max(yy, 0), Hh - 1);
        int xc = min(max(xx, 0), Ww - 1);
        ioff[t] = yc * Ww + xc;
    }

    const float* xb = x + (size_t)b * Cc * HWp;

    for (int c = 0; c < 64; c++) {
        const float* xc = xb + c * HWp;
        float v[9];
#pragma unroll
        for (int t = 0; t < 9; t++) v[t] = vld[t] ? __ldg(xc + ioff[t]) : 0.f;
#pragma unroll
        for (int t = 0; t < 9; t++) {
            unsigned long long vv = pk2(v[t], v[t]);
            const ulonglong2* wr = (const ulonglong2*)(Wsh + (c * 9 + t) * 28);
#pragma unroll
            for (int u = 0; u < 7; u++) {
                ulonglong2 w2 = wr[u];
                fma2(acc[2 * u],     w2.x, vv);
                fma2(acc[2 * u + 1], w2.y, vv);
            }
        }
    }

    float accf[28];
#pragma unroll
    for (int u = 0; u < 14; u++) upk2(acc[u], accf[2 * u], accf[2 * u + 1]);

#pragma unroll
    for (int k = 0; k < 9; k++) {
        float offy = accf[2 * k];
        float offx = accf[2 * k + 1];
        float m = 1.f / (1.f + expf(-accf[18 + k]));
        float py = offy + (float)(i - 1 + k / 3);
        float px = offx + (float)(j - 1 + k % 3);
        int o = (b * 9 + k) * HWp + p;
        g_py[o] = py;
        g_px[o] = px;
        g_m[o]  = m;
    }
}

// ============================================================================
// Kernel 2: per 128-pixel tile: for each tap k, sample masked bilinear tile
// S[64][128] into smem, then GEMM-accumulate out[64][128] += Wk[64][64] * S.
// 256 threads; each thread owns 8 outch x 8 pixels, where the 8 pixels are
// TWO 16B groups (tx*4 and 64+tx*4) so S LDS.128 reads are conflict-free
// (consecutive lanes -> consecutive 16B).
// ============================================================================
__global__ void __launch_bounds__(256) dcn_kernel(
    const float* __restrict__ x,
    const float* __restrict__ dw,
    float* __restrict__ out)
{
    extern __shared__ float sm[];
    float* Ws = sm;           // [64 c][64 o] = 4096 floats
    float* S  = sm + 4096;    // [64 c][128 pix] = 8192 floats

    const int tid = threadIdx.x;
    const int b = blockIdx.x / 200;                // 200 tiles per image
    const int pbase = (blockIdx.x % 200) * 128;    // in-image pixel base
    const int tx = tid & 15;                       // pixel-group id (16 groups)
    const int ty = tid >> 4;                       // o-group id (16 groups of 4o)

    const int pix = tid & 127;                     // sampling role
    const int cg  = tid >> 7;                      // channel half (0/1)
    const float* xb = x + (size_t)(b * 64 + cg * 32) * HWp;

    unsigned long long acc[4][4];
#pragma unroll
    for (int oi = 0; oi < 4; oi++)
#pragma unroll
        for (int pp = 0; pp < 4; pp++) acc[oi][pp] = 0ull;

    for (int k = 0; k < 9; k++) {
        __syncthreads();  // protect Ws/S from previous GEMM readers

        // --- stage Wk: Ws[c*64+o] = dcn_w[o][c][k] ---
#pragma unroll
        for (int r = 0; r < 16; r++) {
            int idx = tid + r * 256;               // 0..4095
            int c = idx >> 6;
            int o = idx & 63;
            Ws[idx] = __ldg(dw + (o * 64 + c) * 9 + k);
        }

        // --- sampling: S[c][pix] = mask * bilinear(x, py, px) ---
        {
            int gi = (b * 9 + k) * HWp + pbase + pix;
            float py = g_py[gi], px = g_px[gi], m = g_m[gi];
            float y0f = floorf(py), x0f = floorf(px);
            int y0 = (int)y0f, x0 = (int)x0f;
            float wy1 = py - y0f, wx1 = px - x0f;
            float wy0 = 1.f - wy1, wx0 = 1.f - wx1;
            bool yv0 = (y0 >= 0) && (y0 < Hh);
            bool yv1 = (y0 + 1 >= 0) && (y0 + 1 < Hh);
            bool xv0 = (x0 >= 0) && (x0 < Ww);
            bool xv1 = (x0 + 1 >= 0) && (x0 + 1 < Ww);
            float w00 = (yv0 && xv0) ? wy0 * wx0 * m : 0.f;
            float w01 = (yv0 && xv1) ? wy0 * wx1 * m : 0.f;
            float w10 = (yv1 && xv0) ? wy1 * wx0 * m : 0.f;
            float w11 = (yv1 && xv1) ? wy1 * wx1 * m : 0.f;
            int y0c = min(max(y0, 0), Hh - 1);
            int y1c = min(max(y0 + 1, 0), Hh - 1);
            int x0c = min(max(x0, 0), Ww - 1);
            int x1c = min(max(x0 + 1, 0), Ww - 1);
            int i00 = y0c * Ww + x0c, i01 = y0c * Ww + x1c;
            int i10 = y1c * Ww + x0c, i11 = y1c * Ww + x1c;
#pragma unroll 4
            for (int c = 0; c < 32; c++) {
                const float* xc = xb + c * HWp;
                float s = w00 * __ldg(xc + i00) + w01 * __ldg(xc + i01)
                        + w10 * __ldg(xc + i10) + w11 * __ldg(xc + i11);
                S[(cg * 32 + c) * 128 + pix] = s;
            }
        }
        __syncthreads();

        // --- GEMM: acc[4o][2x4pix] += Wk^T * S ---
        // thread's pixels: [tx*4 .. tx*4+3] and [64+tx*4 .. 64+tx*4+3]
        {
            const float4*     Ws4 = (const float4*)Ws;
            const ulonglong2* Su2 = (const ulonglong2*)S;   // 16B units
#pragma unroll 8
            for (int cc = 0; cc < 64; cc++) {
                float4 av = Ws4[cc * 16 + ty];
                ulonglong2 b0 = Su2[cc * 32 + tx];        // pixels tx*4..+3
                ulonglong2 b1 = Su2[cc * 32 + 16 + tx];   // pixels 64+tx*4..+3
                unsigned long long a0 = pk2(av.x, av.x);
                unsigned long long a1 = pk2(av.y, av.y);
                unsigned long long a2 = pk2(av.z, av.z);
                unsigned long long a3 = pk2(av.w, av.w);
                fma2(acc[0][0], a0, b0.x); fma2(acc[0][1], a0, b0.y);
                fma2(acc[0][2], a0, b1.x); fma2(acc[0][3], a0, b1.y);
                fma2(acc[1][0], a1, b0.x); fma2(acc[1][1], a1, b0.y);
                fma2(acc[1][2], a1, b1.x); fma2(acc[1][3], a1, b1.y);
                fma2(acc[2][0], a2, b0.x); fma2(acc[2][1], a2, b0.y);
                fma2(acc[2][2], a2, b1.x); fma2(acc[2][3], a2, b1.y);
                fma2(acc[3][0], a3, b0.x); fma2(acc[3][1], a3, b0.y);
                fma2(acc[3][2], a3, b1.x); fma2(acc[3][3], a3, b1.y);
            }
        }
    }

    // --- epilogue: two float4 groups per o ---
    const int p0a = pbase + tx * 4;
    const int p0b = pbase + 64 + tx * 4;
    float* obp = out + (size_t)(b * 64 + ty * 4) * HWp;
#pragma unroll
    for (int oi = 0; oi < 4; oi++) {
        float4 v0, v1;
        upk2(acc[oi][0], v0.x, v0.y);
        upk2(acc[oi][1], v0.z, v0.w);
        upk2(acc[oi][2], v1.x, v1.y);
        upk2(acc[oi][3], v1.z, v1.w);
        *(float4*)(obp + (size_t)oi * HWp + p0a) = v0;
        *(float4*)(obp + (size_t)oi * HWp + p0b) = v1;
    }
}

extern "C" void kernel_launch(void* const* d_in, const int* in_sizes, int n_in,
                              void* d_out, int out_size)
{
    const float* x        = (const float*)d_in[0];
    const float* offset_w = (const float*)d_in[1];
    const float* offset_b = (const float*)d_in[2];
    const float* mask_w   = (const float*)d_in[3];
    const float* mask_b   = (const float*)d_in[4];
    const float* dcn_w    = (const float*)d_in[5];
    float* out = (float*)d_out;

    const int smem1 = 64 * 9 * 28 * 4;   // 64512 B
    const int smem2 = (4096 + 8192) * 4; // 49152 B
    cudaFuncSetAttribute(omconv_kernel, cudaFuncAttributeMaxDynamicSharedMemorySize, smem1);
    cudaFuncSetAttribute(dcn_kernel,    cudaFuncAttributeMaxDynamicSharedMemorySize, smem2);

    omconv_kernel<<<400, 256, smem1>>>(x, offset_w, offset_b, mask_w, mask_b);
    dcn_kernel<<<800, 256, smem2>>>(x, dcn_w, out);
}

// round 5
// speedup vs baseline: 1.6364x; 1.3551x over previous
#include <cuda_runtime.h>
#include <math.h>

#define Hh 160
#define Ww 160
#define HWp 25600
#define Cc 64
#define OUTC 64
#define Bb 4

// scratch: precomputed sample coords + mask, [B][9][H*W]
__device__ float g_py[Bb * 9 * HWp];
__device__ float g_px[Bb * 9 * HWp];
__device__ float g_m [Bb * 9 * HWp];

__device__ __forceinline__ unsigned long long pk2(float lo, float hi) {
    unsigned long long r;
    asm("mov.b64 %0,{%1,%2};" : "=l"(r) : "f"(lo), "f"(hi));
    return r;
}
__device__ __forceinline__ void upk2(unsigned long long v, float& lo, float& hi) {
    asm("mov.b64 {%0,%1},%2;" : "=f"(lo), "=f"(hi) : "l"(v));
}
__device__ __forceinline__ void fma2(unsigned long long& d, unsigned long long a, unsigned long long b) {
    asm("fma.rn.f32x2 %0,%1,%2,%0;" : "+l"(d) : "l"(a), "l"(b));
}

// ============================================================================
// Kernel 1: offset(18ch)+mask(9ch) 3x3 conv. 128 threads, 2 pixels/thread
// (pix tid and tid+128 of a 256-pixel chunk) so each broadcast weight
// LDS.128 feeds 4 fma2 instead of 2.
// ============================================================================
__global__ void __launch_bounds__(128) omconv_kernel(
    const float* __restrict__ x,
    const float* __restrict__ ow, const float* __restrict__ ob,
    const float* __restrict__ mw, const float* __restrict__ mb)
{
    extern __shared__ float Wsh[];  // [64][9][28] = 16128 floats (row = 112B)
    const int tid = threadIdx.x;

    for (int idx = tid; idx < 64 * 9 * 28; idx += 128) {
        int o = idx % 28;
        int ck = idx / 28;
        int t = ck % 9;
        int c = ck / 9;
        float w;
        if (o < 18)      w = ow[(o * 64 + c) * 9 + t];
        else if (o < 27) w = mw[((o - 18) * 64 + c) * 9 + t];
        else             w = 0.f;
        Wsh[idx] = w;
    }
    __syncthreads();

    const int base = blockIdx.x * 256;          // 400 * 256 = 102400
    const int b = base / HWp;                   // chunk never crosses b
    const int pbb = base - b * HWp;

    int pl[2];  pl[0] = pbb + tid;  pl[1] = pbb + tid + 128;
    int ii[2], jj[2];
    int  ioff[2][9];
    bool vld[2][9];
#pragma unroll
    for (int q = 0; q < 2; q++) {
        ii[q] = pl[q] / Ww;
        jj[q] = pl[q] - ii[q] * Ww;
#pragma unroll
        for (int t = 0; t < 9; t++) {
            int yy = ii[q] + t / 3 - 1;
            int xx = jj[q] + t % 3 - 1;
            vld[q][t] = (yy >= 0) && (yy < Hh) && (xx >= 0) && (xx < Ww);
            int yc = min(max(yy, 0), Hh - 1);
            int xc = min(max(xx, 0), Ww - 1);
            ioff[q][t] = yc * Ww + xc;
        }
    }

    unsigned long long acc[2][14];
#pragma unroll
    for (int u = 0; u < 14; u++) {
        int o0 = 2 * u, o1 = 2 * u + 1;
        float blo = (o0 < 18) ? ob[o0] : mb[o0 - 18];
        float bhi = (o1 < 18) ? ob[o1] : ((o1 < 27) ? mb[o1 - 18] : 0.f);
        unsigned long long bb = pk2(blo, bhi);
        acc[0][u] = bb;  acc[1][u] = bb;
    }

    const float* xb = x + (size_t)b * Cc * HWp;

    for (int c = 0; c < 64; c++) {
        const float* xc = xb + c * HWp;
        float v[2][9];
#pragma unroll
        for (int q = 0; q < 2; q++)
#pragma unroll
            for (int t = 0; t < 9; t++)
                v[q][t] = vld[q][t] ? __ldg(xc + ioff[q][t]) : 0.f;
#pragma unroll
        for (int t = 0; t < 9; t++) {
            unsigned long long v0 = pk2(v[0][t], v[0][t]);
            unsigned long long v1 = pk2(v[1][t], v[1][t]);
            const ulonglong2* wr = (const ulonglong2*)(Wsh + (c * 9 + t) * 28);
#pragma unroll
            for (int u = 0; u < 7; u++) {
                ulonglong2 w2 = wr[u];
                fma2(acc[0][2 * u],     w2.x, v0);
                fma2(acc[0][2 * u + 1], w2.y, v0);
                fma2(acc[1][2 * u],     w2.x, v1);
                fma2(acc[1][2 * u + 1], w2.y, v1);
            }
        }
    }

#pragma unroll
    for (int q = 0; q < 2; q++) {
        float accf[28];
#pragma unroll
        for (int u = 0; u < 14; u++) upk2(acc[q][u], accf[2 * u], accf[2 * u + 1]);
#pragma unroll
        for (int k = 0; k < 9; k++) {
            float m = 1.f / (1.f + expf(-accf[18 + k]));
            float py = accf[2 * k]     + (float)(ii[q] - 1 + k / 3);
            float px = accf[2 * k + 1] + (float)(jj[q] - 1 + k % 3);
            int o = (b * 9 + k) * HWp + pl[q];
            g_py[o] = py;
            g_px[o] = px;
            g_m[o]  = m;
        }
    }
}

// ============================================================================
// Kernel 2: per 256-pixel tile: for each tap k, sample masked bilinear tile
// S[64][256] into smem, then GEMM out[64][256] += Wk[64][64] * S.
// 256 threads: sampling = 1 pixel/thread x 64 c; GEMM = 8 outch x 8 pix per
// thread (pixels as two 16B groups tx*4 and 128+tx*4 -> conflict-free
// LDS.128; A-loads are warp-broadcast). 4 LDS.128 : 32 fma2 per cc.
// ============================================================================
__global__ void __launch_bounds__(256, 2) dcn_kernel(
    const float* __restrict__ x,
    const float* __restrict__ dw,
    float* __restrict__ out)
{
    extern __shared__ float sm[];
    float* Ws = sm;           // [64 c][64 o] = 4096 floats
    float* S  = sm + 4096;    // [64 c][256 pix] = 16384 floats

    const int tid = threadIdx.x;
    const int b = blockIdx.x / 100;                // 100 tiles per image
    const int pbase = (blockIdx.x % 100) * 256;
    const int tx = tid & 31;                       // pixel-group (32 groups)
    const int ty = tid >> 5;                       // o-group (8 groups of 8o)

    const float* xb = x + (size_t)b * 64 * HWp;

    unsigned long long acc[8][4];
#pragma unroll
    for (int oi = 0; oi < 8; oi++)
#pragma unroll
        for (int pp = 0; pp < 4; pp++) acc[oi][pp] = 0ull;

    for (int k = 0; k < 9; k++) {
        __syncthreads();  // protect Ws/S from previous GEMM readers

        // --- stage Wk: Ws[c*64+o] = dcn_w[o][c][k] ---
#pragma unroll
        for (int r = 0; r < 16; r++) {
            int idx = tid + r * 256;               // 0..4095
            int c = idx >> 6;
            int o = idx & 63;
            Ws[idx] = __ldg(dw + (o * 64 + c) * 9 + k);
        }

        // --- sampling: S[c][tid] = mask * bilinear(x, py, px), all 64 c ---
        {
            int gi = (b * 9 + k) * HWp + pbase + tid;
            float py = g_py[gi], px = g_px[gi], m = g_m[gi];
            float y0f = floorf(py), x0f = floorf(px);
            int y0 = (int)y0f, x0 = (int)x0f;
            float wy1 = py - y0f, wx1 = px - x0f;
            float wy0 = 1.f - wy1, wx0 = 1.f - wx1;
            bool yv0 = (y0 >= 0) && (y0 < Hh);
            bool yv1 = (y0 + 1 >= 0) && (y0 + 1 < Hh);
            bool xv0 = (x0 >= 0) && (x0 < Ww);
            bool xv1 = (x0 + 1 >= 0) && (x0 + 1 < Ww);
            float w00 = (yv0 && xv0) ? wy0 * wx0 * m : 0.f;
            float w01 = (yv0 && xv1) ? wy0 * wx1 * m : 0.f;
            float w10 = (yv1 && xv0) ? wy1 * wx0 * m : 0.f;
            float w11 = (yv1 && xv1) ? wy1 * wx1 * m : 0.f;
            int y0c = min(max(y0, 0), Hh - 1);
            int y1c = min(max(y0 + 1, 0), Hh - 1);
            int x0c = min(max(x0, 0), Ww - 1);
            int x1c = min(max(x0 + 1, 0), Ww - 1);
            int i00 = y0c * Ww + x0c, i01 = y0c * Ww + x1c;
            int i10 = y1c * Ww + x0c, i11 = y1c * Ww + x1c;
#pragma unroll 4
            for (int c = 0; c < 64; c++) {
                const float* xc = xb + c * HWp;
                float s = w00 * __ldg(xc + i00) + w01 * __ldg(xc + i01)
                        + w10 * __ldg(xc + i10) + w11 * __ldg(xc + i11);
                S[c * 256 + tid] = s;
            }
        }
        __syncthreads();

        // --- GEMM: acc[8o][2x4pix] += Wk^T * S ---
        {
            const float4*     Ws4 = (const float4*)Ws;
            const ulonglong2* Su2 = (const ulonglong2*)S;   // 16B units
#pragma unroll 4
            for (int cc = 0; cc < 64; cc++) {
                float4 av0 = Ws4[cc * 16 + ty * 2];
                float4 av1 = Ws4[cc * 16 + ty * 2 + 1];
                ulonglong2 b0 = Su2[cc * 64 + tx];        // pixels tx*4..+3
                ulonglong2 b1 = Su2[cc * 64 + 32 + tx];   // pixels 128+tx*4..+3
                unsigned long long a0 = pk2(av0.x, av0.x);
                unsigned long long a1 = pk2(av0.y, av0.y);
                unsigned long long a2 = pk2(av0.z, av0.z);
                unsigned long long a3 = pk2(av0.w, av0.w);
                unsigned long long a4 = pk2(av1.x, av1.x);
                unsigned long long a5 = pk2(av1.y, av1.y);
                unsigned long long a6 = pk2(av1.z, av1.z);
                unsigned long long a7 = pk2(av1.w, av1.w);
                fma2(acc[0][0], a0, b0.x); fma2(acc[0][1], a0, b0.y);
                fma2(acc[0][2], a0, b1.x); fma2(acc[0][3], a0, b1.y);
                fma2(acc[1][0], a1, b0.x); fma2(acc[1][1], a1, b0.y);
                fma2(acc[1][2], a1, b1.x); fma2(acc[1][3], a1, b1.y);
                fma2(acc[2][0], a2, b0.x); fma2(acc[2][1], a2, b0.y);
                fma2(acc[2][2], a2, b1.x); fma2(acc[2][3], a2, b1.y);
                fma2(acc[3][0], a3, b0.x); fma2(acc[3][1], a3, b0.y);
                fma2(acc[3][2], a3, b1.x); fma2(acc[3][3], a3, b1.y);
                fma2(acc[4][0], a4, b0.x); fma2(acc[4][1], a4, b0.y);
                fma2(acc[4][2], a4, b1.x); fma2(acc[4][3], a4, b1.y);
                fma2(acc[5][0], a5, b0.x); fma2(acc[5][1], a5, b0.y);
                fma2(acc[5][2], a5, b1.x); fma2(acc[5][3], a5, b1.y);
                fma2(acc[6][0], a6, b0.x); fma2(acc[6][1], a6, b0.y);
                fma2(acc[6][2], a6, b1.x); fma2(acc[6][3], a6, b1.y);
                fma2(acc[7][0], a7, b0.x); fma2(acc[7][1], a7, b0.y);
                fma2(acc[7][2], a7, b1.x); fma2(acc[7][3], a7, b1.y);
            }
        }
    }

    // --- epilogue: 8 o rows, two float4 groups each ---
    const int p0a = pbase + tx * 4;
    const int p0b = pbase + 128 + tx * 4;
    float* obp = out + (size_t)(b * 64 + ty * 8) * HWp;
#pragma unroll
    for (int oi = 0; oi < 8; oi++) {
        float4 v0, v1;
        upk2(acc[oi][0], v0.x, v0.y);
        upk2(acc[oi][1], v0.z, v0.w);
        upk2(acc[oi][2], v1.x, v1.y);
        upk2(acc[oi][3], v1.z, v1.w);
        *(float4*)(obp + (size_t)oi * HWp + p0a) = v0;
        *(float4*)(obp + (size_t)oi * HWp + p0b) = v1;
    }
}

extern "C" void kernel_launch(void* const* d_in, const int* in_sizes, int n_in,
                              void* d_out, int out_size)
{
    const float* x        = (const float*)d_in[0];
    const float* offset_w = (const float*)d_in[1];
    const float* offset_b = (const float*)d_in[2];
    const float* mask_w   = (const float*)d_in[3];
    const float* mask_b   = (const float*)d_in[4];
    const float* dcn_w    = (const float*)d_in[5];
    float* out = (float*)d_out;

    const int smem1 = 64 * 9 * 28 * 4;      // 64512 B
    const int smem2 = (4096 + 16384) * 4;   // 81920 B
    cudaFuncSetAttribute(omconv_kernel, cudaFuncAttributeMaxDynamicSharedMemorySize, smem1);
    cudaFuncSetAttribute(dcn_kernel,    cudaFuncAttributeMaxDynamicSharedMemorySize, smem2);

    omconv_kernel<<<400, 128, smem1>>>(x, offset_w, offset_b, mask_w, mask_b);
    dcn_kernel<<<400, 256, smem2>>>(x, dcn_w, out);
}

// round 7
// speedup vs baseline: 1.6981x; 1.0377x over previous
#include <cuda_runtime.h>
#include <math.h>
#include <cstdint>

#define Hh 160
#define Ww 160
#define HWp 25600
#define Cc 64
#define OUTC 64
#define Bb 4

// scratch: precomputed sample coords + mask, [B][9][H*W]
__device__ float g_py[Bb * 9 * HWp];
__device__ float g_px[Bb * 9 * HWp];
__device__ float g_m [Bb * 9 * HWp];

__device__ __forceinline__ unsigned long long pk2(float lo, float hi) {
    unsigned long long r;
    asm("mov.b64 %0,{%1,%2};" : "=l"(r) : "f"(lo), "f"(hi));
    return r;
}
__device__ __forceinline__ void upk2(unsigned long long v, float& lo, float& hi) {
    asm("mov.b64 {%0,%1},%2;" : "=f"(lo), "=f"(hi) : "l"(v));
}
__device__ __forceinline__ void fma2(unsigned long long& d, unsigned long long a, unsigned long long b) {
    asm("fma.rn.f32x2 %0,%1,%2,%0;" : "+l"(d) : "l"(a), "l"(b));
}

__device__ __forceinline__ uint32_t smem_to_u32(const void* p) {
    uint32_t a;
    asm("{ .reg .u64 t; cvta.to.shared.u64 t, %1; cvt.u32.u64 %0, t; }" : "=r"(a) : "l"(p));
    return a;
}
#define MBARRIER_INIT(mb, c) \
    asm volatile("mbarrier.init.shared.b64 [%0], %1;" :: "r"((uint32_t)(mb)), "r"((uint32_t)(c)) : "memory")
#define MBARRIER_ARRIVE(mb) \
    asm volatile("mbarrier.arrive.shared.b64 _, [%0];" :: "r"((uint32_t)(mb)) : "memory")
#define MBARRIER_WAIT_PARITY(mb, par) do {                                              \
    uint32_t _m = (uint32_t)(mb); uint32_t _p = (uint32_t)(par); uint32_t _d;           \
    asm volatile("{\n\t.reg .pred p;\n\t"                                               \
        "mbarrier.try_wait.parity.acquire.cta.shared::cta.b64 p, [%1], %2;\n\t"         \
        "selp.b32 %0, 1, 0, p;\n\t}" : "=r"(_d) : "r"(_m), "r"(_p) : "memory");         \
    if (!_d) {                                                                          \
        asm volatile("{\n\t.reg .pred P1;\n\t"                                          \
            "WL_%=:\n\t"                                                                \
            "mbarrier.try_wait.parity.acquire.cta.shared::cta.b64 P1, [%0], %1, 0x989680;\n\t" \
            "@P1 bra.uni WD_%=;\n\t"                                                    \
            "bra.uni WL_%=;\n\t"                                                        \
            "WD_%=:\n\t}" :: "r"(_m), "r"(_p) : "memory");                              \
    }                                                                                   \
} while (0)

// ============================================================================
// Kernel 1: offset(18ch)+mask(9ch) 3x3 conv. 128 threads, 2 pixels/thread.
// (unchanged from round 4/5)
// ============================================================================
__global__ void __launch_bounds__(128) omconv_kernel(
    const float* __restrict__ x,
    const float* __restrict__ ow, const float* __restrict__ ob,
    const float* __restrict__ mw, const float* __restrict__ mb)
{
    extern __shared__ float Wsh[];  // [64][9][28]
    const int tid = threadIdx.x;

    for (int idx = tid; idx < 64 * 9 * 28; idx += 128) {
        int o = idx % 28;
        int ck = idx / 28;
        int t = ck % 9;
        int c = ck / 9;
        float w;
        if (o < 18)      w = ow[(o * 64 + c) * 9 + t];
        else if (o < 27) w = mw[((o - 18) * 64 + c) * 9 + t];
        else             w = 0.f;
        Wsh[idx] = w;
    }
    __syncthreads();

    const int base = blockIdx.x * 256;
    const int b = base / HWp;
    const int pbb = base - b * HWp;

    int pl[2];  pl[0] = pbb + tid;  pl[1] = pbb + tid + 128;
    int ii[2], jj[2];
    int  ioff[2][9];
    bool vld[2][9];
#pragma unroll
    for (int q = 0; q < 2; q++) {
        ii[q] = pl[q] / Ww;
        jj[q] = pl[q] - ii[q] * Ww;
#pragma unroll
        for (int t = 0; t < 9; t++) {
            int yy = ii[q] + t / 3 - 1;
            int xx = jj[q] + t % 3 - 1;
            vld[q][t] = (yy >= 0) && (yy < Hh) && (xx >= 0) && (xx < Ww);
            int yc = min(max(yy, 0), Hh - 1);
            int xc = min(max(xx, 0), Ww - 1);
            ioff[q][t] = yc * Ww + xc;
        }
    }

    unsigned long long acc[2][14];
#pragma unroll
    for (int u = 0; u < 14; u++) {
        int o0 = 2 * u, o1 = 2 * u + 1;
        float blo = (o0 < 18) ? ob[o0] : mb[o0 - 18];
        float bhi = (o1 < 18) ? ob[o1] : ((o1 < 27) ? mb[o1 - 18] : 0.f);
        unsigned long long bb = pk2(blo, bhi);
        acc[0][u] = bb;  acc[1][u] = bb;
    }

    const float* xb = x + (size_t)b * Cc * HWp;

    for (int c = 0; c < 64; c++) {
        const float* xc = xb + c * HWp;
        float v[2][9];
#pragma unroll
        for (int q = 0; q < 2; q++)
#pragma unroll
            for (int t = 0; t < 9; t++)
                v[q][t] = vld[q][t] ? __ldg(xc + ioff[q][t]) : 0.f;
#pragma unroll
        for (int t = 0; t < 9; t++) {
            unsigned long long v0 = pk2(v[0][t], v[0][t]);
            unsigned long long v1 = pk2(v[1][t], v[1][t]);
            const ulonglong2* wr = (const ulonglong2*)(Wsh + (c * 9 + t) * 28);
#pragma unroll
            for (int u = 0; u < 7; u++) {
                ulonglong2 w2 = wr[u];
                fma2(acc[0][2 * u],     w2.x, v0);
                fma2(acc[0][2 * u + 1], w2.y, v0);
                fma2(acc[1][2 * u],     w2.x, v1);
                fma2(acc[1][2 * u + 1], w2.y, v1);
            }
        }
    }

#pragma unroll
    for (int q = 0; q < 2; q++) {
        float accf[28];
#pragma unroll
        for (int u = 0; u < 14; u++) upk2(acc[q][u], accf[2 * u], accf[2 * u + 1]);
#pragma unroll
        for (int k = 0; k < 9; k++) {
            float m = 1.f / (1.f + expf(-accf[18 + k]));
            float py = accf[2 * k]     + (float)(ii[q] - 1 + k / 3);
            float px = accf[2 * k + 1] + (float)(jj[q] - 1 + k % 3);
            int o = (b * 9 + k) * HWp + pl[q];
            g_py[o] = py;
            g_px[o] = px;
            g_m[o]  = m;
        }
    }
}

// ============================================================================
// Kernel 2: warp-specialized DCN GEMM, 512 threads.
//   warps 0-7  (tid 0..255):  GEMM consumers, 8o x 8pix f32x2, acc across taps
//   warps 8-15 (tid 256..511): producers — stage Wk + bilinear-sample
//                              S[64][256] into double-buffered smem
// Buffers: buf[s] = { Ws[64c][64o] (16KB), S[64c][256pix] (64KB) }, s = k&1.
// Sync: mbarriers full[2]/empty[2], 256-thread arrive counts, parity (k>>1)&1.
// ============================================================================
static constexpr int TILE     = 256;
static constexpr int MB_FULL0 = 0;    // +s*8
static constexpr int MB_EMPT0 = 16;   // +s*8
static constexpr int BUF0     = 128;               // bytes
static constexpr int BUFSZ    = (4096 + 64 * TILE) * 4;   // 81920 B
static constexpr int SMEM_WS  = BUF0 + 2 * BUFSZ;  // 163968 B

__global__ void __launch_bounds__(512, 1) dcn_ws_kernel(
    const float* __restrict__ x,
    const float* __restrict__ dw,
    float* __restrict__ out)
{
    extern __shared__ char smc[];
    const uint32_t sb = smem_to_u32(smc);
    const int tid = threadIdx.x;

    const int b = blockIdx.x / 100;               // 100 tiles of 256 pix per image
    const int pbase = (blockIdx.x % 100) * TILE;

    if (tid == 0) {
        MBARRIER_INIT(sb + MB_FULL0,     256);
        MBARRIER_INIT(sb + MB_FULL0 + 8, 256);
        MBARRIER_INIT(sb + MB_EMPT0,     256);
        MBARRIER_INIT(sb + MB_EMPT0 + 8, 256);
    }
    __syncthreads();

    if (tid >= 256) {
        // ---------------- PRODUCER ----------------
        const int stid = tid - 256;               // 0..255 = pixel in tile
        const float* xb = x + (size_t)b * 64 * HWp;

        // precompute sample geometry base index
        for (int k = 0; k < 9; k++) {
            const int s = k & 1;
            const int n = k >> 1;
            if (k >= 2) MBARRIER_WAIT_PARITY(sb + MB_EMPT0 + s * 8, (n - 1) & 1);

            float* Ws   = (float*)(smc + BUF0 + s * BUFSZ);
            float* Sbuf = Ws + 4096;

            // stage Wk: Ws[c*64+o] = dcn_w[o][c][k], 16 entries/thread
#pragma unroll
            for (int r = 0; r < 16; r++) {
                int idx = stid + r * 256;         // 0..4095, = c*64+o
                int c = idx >> 6;
                int o = idx & 63;
                Ws[idx] = __ldg(dw + (o * 64 + c) * 9 + k);
            }

            // sample pixel stid for all 64 channels
            {
                int gi = (b * 9 + k) * HWp + pbase + stid;
                float py = g_py[gi], px = g_px[gi], m = g_m[gi];
                float y0f = floorf(py), x0f = floorf(px);
                int y0 = (int)y0f, x0 = (int)x0f;
                float wy1 = py - y0f, wx1 = px - x0f;
                float wy0 = 1.f - wy1, wx0 = 1.f - wx1;
                bool yv0 = (y0 >= 0) && (y0 < Hh);
                bool yv1 = (y0 + 1 >= 0) && (y0 + 1 < Hh);
                bool xv0 = (x0 >= 0) && (x0 < Ww);
                bool xv1 = (x0 + 1 >= 0) && (x0 + 1 < Ww);
                float w00 = (yv0 && xv0) ? wy0 * wx0 * m : 0.f;
                float w01 = (yv0 && xv1) ? wy0 * wx1 * m : 0.f;
                float w10 = (yv1 && xv0) ? wy1 * wx0 * m : 0.f;
                float w11 = (yv1 && xv1) ? wy1 * wx1 * m : 0.f;
                int y0c = min(max(y0, 0), Hh - 1);
                int y1c = min(max(y0 + 1, 0), Hh - 1);
                int x0c = min(max(x0, 0), Ww - 1);
                int x1c = min(max(x0 + 1, 0), Ww - 1);
                int i00 = y0c * Ww + x0c, i01 = y0c * Ww + x1c;
                int i10 = y1c * Ww + x0c, i11 = y1c * Ww + x1c;
#pragma unroll 4
                for (int c = 0; c < 64; c++) {
                    const float* xc = xb + (size_t)c * HWp;
                    float sv = w00 * __ldg(xc + i00) + w01 * __ldg(xc + i01)
                             + w10 * __ldg(xc + i10) + w11 * __ldg(xc + i11);
                    Sbuf[c * TILE + stid] = sv;
                }
            }

            MBARRIER_ARRIVE(sb + MB_FULL0 + s * 8);
        }
    } else {
        // ---------------- CONSUMER (GEMM) ----------------
        const int tx = tid & 31;                  // pixel-group (32 groups)
        const int ty = tid >> 5;                  // o-group (8 groups of 8o)

        unsigned long long acc[8][4];
#pragma unroll
        for (int oi = 0; oi < 8; oi++)
#pragma unroll
            for (int pp = 0; pp < 4; pp++) acc[oi][pp] = 0ull;

        for (int k = 0; k < 9; k++) {
            const int s = k & 1;
            const int n = k >> 1;
            MBARRIER_WAIT_PARITY(sb + MB_FULL0 + s * 8, n & 1);

            const float4*     Ws4 = (const float4*)(smc + BUF0 + s * BUFSZ);
            const ulonglong2* Su2 = (const ulonglong2*)(smc + BUF0 + s * BUFSZ + 16384);

#pragma unroll 4
            for (int cc = 0; cc < 64; cc++) {
                float4 av0 = Ws4[cc * 16 + ty * 2];
                float4 av1 = Ws4[cc * 16 + ty * 2 + 1];
                ulonglong2 b0 = Su2[cc * 64 + tx];        // pixels tx*4..+3
                ulonglong2 b1 = Su2[cc * 64 + 32 + tx];   // pixels 128+tx*4..+3
                unsigned long long a0 = pk2(av0.x, av0.x);
                unsigned long long a1 = pk2(av0.y, av0.y);
                unsigned long long a2 = pk2(av0.z, av0.z);
                unsigned long long a3 = pk2(av0.w, av0.w);
                unsigned long long a4 = pk2(av1.x, av1.x);
                unsigned long long a5 = pk2(av1.y, av1.y);
                unsigned long long a6 = pk2(av1.z, av1.z);
                unsigned long long a7 = pk2(av1.w, av1.w);
                fma2(acc[0][0], a0, b0.x); fma2(acc[0][1], a0, b0.y);
                fma2(acc[0][2], a0, b1.x); fma2(acc[0][3], a0, b1.y);
                fma2(acc[1][0], a1, b0.x); fma2(acc[1][1], a1, b0.y);
                fma2(acc[1][2], a1, b1.x); fma2(acc[1][3], a1, b1.y);
                fma2(acc[2][0], a2, b0.x); fma2(acc[2][1], a2, b0.y);
                fma2(acc[2][2], a2, b1.x); fma2(acc[2][3], a2, b1.y);
                fma2(acc[3][0], a3, b0.x); fma2(acc[3][1], a3, b0.y);
                fma2(acc[3][2], a3, b1.x); fma2(acc[3][3], a3, b1.y);
                fma2(acc[4][0], a4, b0.x); fma2(acc[4][1], a4, b0.y);
                fma2(acc[4][2], a4, b1.x); fma2(acc[4][3], a4, b1.y);
                fma2(acc[5][0], a5, b0.x); fma2(acc[5][1], a5, b0.y);
                fma2(acc[5][2], a5, b1.x); fma2(acc[5][3], a5, b1.y);
                fma2(acc[6][0], a6, b0.x); fma2(acc[6][1], a6, b0.y);
                fma2(acc[6][2], a6, b1.x); fma2(acc[6][3], a6, b1.y);
                fma2(acc[7][0], a7, b0.x); fma2(acc[7][1], a7, b0.y);
                fma2(acc[7][2], a7, b1.x); fma2(acc[7][3], a7, b1.y);
            }

            MBARRIER_ARRIVE(sb + MB_EMPT0 + s * 8);
        }

        // epilogue: 8 o rows, two float4 groups each
        const int p0a = pbase + tx * 4;
        const int p0b = pbase + 128 + tx * 4;
        float* obp = out + (size_t)(b * 64 + ty * 8) * HWp;
#pragma unroll
        for (int oi = 0; oi < 8; oi++) {
            float4 v0, v1;
            upk2(acc[oi][0], v0.x, v0.y);
            upk2(acc[oi][1], v0.z, v0.w);
            upk2(acc[oi][2], v1.x, v1.y);
            upk2(acc[oi][3], v1.z, v1.w);
            *(float4*)(obp + (size_t)oi * HWp + p0a) = v0;
            *(float4*)(obp + (size_t)oi * HWp + p0b) = v1;
        }
    }
}

extern "C" void kernel_launch(void* const* d_in, const int* in_sizes, int n_in,
                              void* d_out, int out_size)
{
    const float* x        = (const float*)d_in[0];
    const float* offset_w = (const float*)d_in[1];
    const float* offset_b = (const float*)d_in[2];
    const float* mask_w   = (const float*)d_in[3];
    const float* mask_b   = (const float*)d_in[4];
    const float* dcn_w    = (const float*)d_in[5];
    float* out = (float*)d_out;

    const int smem1 = 64 * 9 * 28 * 4;      // 64512 B
    cudaFuncSetAttribute(omconv_kernel, cudaFuncAttributeMaxDynamicSharedMemorySize, smem1);
    cudaFuncSetAttribute(dcn_ws_kernel, cudaFuncAttributeMaxDynamicSharedMemorySize, SMEM_WS);

    omconv_kernel<<<400, 128, smem1>>>(x, offset_w, offset_b, mask_w, mask_b);
    dcn_ws_kernel<<<400, 512, SMEM_WS>>>(x, dcn_w, out);
}

// round 8
// speedup vs baseline: 1.8383x; 1.0825x over previous
#include <cuda_runtime.h>
#include <math.h>
#include <cstdint>

#define Hh 160
#define Ww 160
#define HWp 25600
#define Cc 64
#define OUTC 64
#define Bb 4

// scratch: precomputed sample coords + mask, [B][9][H*W]
__device__ float g_py[Bb * 9 * HWp];
__device__ float g_px[Bb * 9 * HWp];
__device__ float g_m [Bb * 9 * HWp];
// transposed input: [b][pix][c] (c contiguous)
__device__ float g_xT[(size_t)Bb * HWp * Cc];
// transposed dcn weights: [k][c][o]
__device__ float g_dwT[9 * Cc * OUTC];

__device__ __forceinline__ unsigned long long pk2(float lo, float hi) {
    unsigned long long r;
    asm("mov.b64 %0,{%1,%2};" : "=l"(r) : "f"(lo), "f"(hi));
    return r;
}
__device__ __forceinline__ void upk2(unsigned long long v, float& lo, float& hi) {
    asm("mov.b64 {%0,%1},%2;" : "=f"(lo), "=f"(hi) : "l"(v));
}
__device__ __forceinline__ void fma2(unsigned long long& d, unsigned long long a, unsigned long long b) {
    asm("fma.rn.f32x2 %0,%1,%2,%0;" : "+l"(d) : "l"(a), "l"(b));
}

__device__ __forceinline__ uint32_t smem_to_u32(const void* p) {
    uint32_t a;
    asm("{ .reg .u64 t; cvta.to.shared.u64 t, %1; cvt.u32.u64 %0, t; }" : "=r"(a) : "l"(p));
    return a;
}
#define MBARRIER_INIT(mb, c) \
    asm volatile("mbarrier.init.shared.b64 [%0], %1;" :: "r"((uint32_t)(mb)), "r"((uint32_t)(c)) : "memory")
#define MBARRIER_ARRIVE(mb) \
    asm volatile("mbarrier.arrive.shared.b64 _, [%0];" :: "r"((uint32_t)(mb)) : "memory")
#define MBARRIER_WAIT_PARITY(mb, par) do {                                              \
    uint32_t _m = (uint32_t)(mb); uint32_t _p = (uint32_t)(par); uint32_t _d;           \
    asm volatile("{\n\t.reg .pred p;\n\t"                                               \
        "mbarrier.try_wait.parity.acquire.cta.shared::cta.b64 p, [%1], %2;\n\t"         \
        "selp.b32 %0, 1, 0, p;\n\t}" : "=r"(_d) : "r"(_m), "r"(_p) : "memory");         \
    if (!_d) {                                                                          \
        asm volatile("{\n\t.reg .pred P1;\n\t"                                          \
            "WL_%=:\n\t"                                                                \
            "mbarrier.try_wait.parity.acquire.cta.shared::cta.b64 P1, [%0], %1, 0x989680;\n\t" \
            "@P1 bra.uni WD_%=;\n\t"                                                    \
            "bra.uni WL_%=;\n\t"                                                        \
            "WD_%=:\n\t}" :: "r"(_m), "r"(_p) : "memory");                              \
    }                                                                                   \
} while (0)

// ============================================================================
// Prep A: transpose x[b][c][p] -> g_xT[b][p][c]
// ============================================================================
__global__ void __launch_bounds__(256) xpose_kernel(const float* __restrict__ x)
{
    __shared__ float t[32][33];
    const int b  = blockIdx.z;
    const int c0 = blockIdx.y * 32;
    const int p0 = blockIdx.x * 32;
    const int tx = threadIdx.x, ty = threadIdx.y;

    const float* xb = x + ((size_t)b * Cc + c0) * HWp + p0;
#pragma unroll
    for (int i = 0; i < 4; i++)
        t[ty + i * 8][tx] = xb[(size_t)(ty + i * 8) * HWp + tx];
    __syncthreads();
    float* o = g_xT + ((size_t)b * HWp + p0) * Cc + c0;
#pragma unroll
    for (int i = 0; i < 4; i++)
        o[(size_t)(ty + i * 8) * Cc + tx] = t[tx][ty + i * 8];
}

// ============================================================================
// Prep B: transpose dcn_w[o][c][k] -> g_dwT[k][c][o]  (147 KB, one-time)
// ============================================================================
__global__ void __launch_bounds__(256) wpose_kernel(const float* __restrict__ dw)
{
    int idx = blockIdx.x * 256 + threadIdx.x;   // 144*256 = 36864 exactly
    int k = idx >> 12;
    int c = (idx >> 6) & 63;
    int o = idx & 63;
    g_dwT[idx] = dw[(o * 64 + c) * 9 + k];
}

// ============================================================================
// Kernel 1: offset(18ch)+mask(9ch) 3x3 conv. 128 threads, 2 pixels/thread.
// (unchanged)
// ============================================================================
__global__ void __launch_bounds__(128) omconv_kernel(
    const float* __restrict__ x,
    const float* __restrict__ ow, const float* __restrict__ ob,
    const float* __restrict__ mw, const float* __restrict__ mb)
{
    extern __shared__ float Wsh[];  // [64][9][28]
    const int tid = threadIdx.x;

    for (int idx = tid; idx < 64 * 9 * 28; idx += 128) {
        int o = idx % 28;
        int ck = idx / 28;
        int t = ck % 9;
        int c = ck / 9;
        float w;
        if (o < 18)      w = ow[(o * 64 + c) * 9 + t];
        else if (o < 27) w = mw[((o - 18) * 64 + c) * 9 + t];
        else             w = 0.f;
        Wsh[idx] = w;
    }
    __syncthreads();

    const int base = blockIdx.x * 256;
    const int b = base / HWp;
    const int pbb = base - b * HWp;

    int pl[2];  pl[0] = pbb + tid;  pl[1] = pbb + tid + 128;
    int ii[2], jj[2];
    int  ioff[2][9];
    bool vld[2][9];
#pragma unroll
    for (int q = 0; q < 2; q++) {
        ii[q] = pl[q] / Ww;
        jj[q] = pl[q] - ii[q] * Ww;
#pragma unroll
        for (int t = 0; t < 9; t++) {
            int yy = ii[q] + t / 3 - 1;
            int xx = jj[q] + t % 3 - 1;
            vld[q][t] = (yy >= 0) && (yy < Hh) && (xx >= 0) && (xx < Ww);
            int yc = min(max(yy, 0), Hh - 1);
            int xc = min(max(xx, 0), Ww - 1);
            ioff[q][t] = yc * Ww + xc;
        }
    }

    unsigned long long acc[2][14];
#pragma unroll
    for (int u = 0; u < 14; u++) {
        int o0 = 2 * u, o1 = 2 * u + 1;
        float blo = (o0 < 18) ? ob[o0] : mb[o0 - 18];
        float bhi = (o1 < 18) ? ob[o1] : ((o1 < 27) ? mb[o1 - 18] : 0.f);
        unsigned long long bb = pk2(blo, bhi);
        acc[0][u] = bb;  acc[1][u] = bb;
    }

    const float* xb = x + (size_t)b * Cc * HWp;

    for (int c = 0; c < 64; c++) {
        const float* xc = xb + c * HWp;
        float v[2][9];
#pragma unroll
        for (int q = 0; q < 2; q++)
#pragma unroll
            for (int t = 0; t < 9; t++)
                v[q][t] = vld[q][t] ? __ldg(xc + ioff[q][t]) : 0.f;
#pragma unroll
        for (int t = 0; t < 9; t++) {
            unsigned long long v0 = pk2(v[0][t], v[0][t]);
            unsigned long long v1 = pk2(v[1][t], v[1][t]);
            const ulonglong2* wr = (const ulonglong2*)(Wsh + (c * 9 + t) * 28);
#pragma unroll
            for (int u = 0; u < 7; u++) {
                ulonglong2 w2 = wr[u];
                fma2(acc[0][2 * u],     w2.x, v0);
                fma2(acc[0][2 * u + 1], w2.y, v0);
                fma2(acc[1][2 * u],     w2.x, v1);
                fma2(acc[1][2 * u + 1], w2.y, v1);
            }
        }
    }

#pragma unroll
    for (int q = 0; q < 2; q++) {
        float accf[28];
#pragma unroll
        for (int u = 0; u < 14; u++) upk2(acc[q][u], accf[2 * u], accf[2 * u + 1]);
#pragma unroll
        for (int k = 0; k < 9; k++) {
            float m = 1.f / (1.f + expf(-accf[18 + k]));
            float py = accf[2 * k]     + (float)(ii[q] - 1 + k / 3);
            float px = accf[2 * k + 1] + (float)(jj[q] - 1 + k % 3);
            int o = (b * 9 + k) * HWp + pl[q];
            g_py[o] = py;
            g_px[o] = px;
            g_m[o]  = m;
        }
    }
}

// ============================================================================
// Kernel 2: warp-specialized DCN GEMM, 512 threads, tile = 256 pixels.
//   consumers (tid 0..255):   16o x 4pix f32x2 register tile, 4 o-groups
//   producers (tid 256..511): geometry + vectorized c-contiguous gather from
//                             g_xT + swizzled STS into S
// S layout: [64 c][256 pix], row 1KB, 8B-granule swizzle g' = g ^ (c>>2)
//   -> conflict-free producer STS and consumer LDS.64.
// ============================================================================
static constexpr int TILE     = 256;
static constexpr int MB_FULL0 = 0;    // +s*8
static constexpr int MB_EMPT0 = 16;   // +s*8
static constexpr int SCR0     = 128;                      // 2 x 8KB scratch
static constexpr int BUF0     = SCR0 + 16384;             // 16512
static constexpr int BUFSZ    = 16384 + 65536;            // Ws 16KB + S 64KB
static constexpr int SMEM_WS  = BUF0 + 2 * BUFSZ;         // 180352 B

__global__ void __launch_bounds__(512, 1) dcn_ws_kernel(
    float* __restrict__ out)
{
    extern __shared__ char smc[];
    const uint32_t sb = smem_to_u32(smc);
    const int tid = threadIdx.x;

    const int b = blockIdx.x / 100;               // 100 tiles of 256 pix per image
    const int pbase = (blockIdx.x % 100) * TILE;

    if (tid == 0) {
        MBARRIER_INIT(sb + MB_FULL0,     256);
        MBARRIER_INIT(sb + MB_FULL0 + 8, 256);
        MBARRIER_INIT(sb + MB_EMPT0,     256);
        MBARRIER_INIT(sb + MB_EMPT0 + 8, 256);
    }
    __syncthreads();

    if (tid >= 256) {
        // ---------------- PRODUCER ----------------
        const int stid = tid - 256;               // 0..255
        const int wp   = stid >> 5;               // producer warp 0..7
        const int half = (stid >> 4) & 1;
        const int c4   = stid & 15;
        const float* xTb = g_xT + (size_t)b * HWp * Cc;

        for (int k = 0; k < 9; k++) {
            const int s = k & 1;
            const int n = k >> 1;
            if (k >= 2) MBARRIER_WAIT_PARITY(sb + MB_EMPT0 + s * 8, (n - 1) & 1);

            float4* Ws4  = (float4*)(smc + BUF0 + s * BUFSZ);
            float*  Sbuf = (float*)(smc + BUF0 + s * BUFSZ + 16384);
            float4* wbuf = (float4*)(smc + SCR0 + s * 8192);
            int4*   ibuf = (int4*)(smc + SCR0 + s * 8192 + 4096);

            // stage Wk (contiguous from g_dwT[k]) : 4 float4 per thread
            {
                const float4* src = (const float4*)(g_dwT + k * 4096);
#pragma unroll
                for (int r = 0; r < 4; r++)
                    Ws4[stid + r * 256] = __ldg(src + stid + r * 256);
            }

            // phase A: geometry for pixel stid
            {
                int gi = (b * 9 + k) * HWp + pbase + stid;
                float py = g_py[gi], px = g_px[gi], m = g_m[gi];
                float y0f = floorf(py), x0f = floorf(px);
                int y0 = (int)y0f, x0 = (int)x0f;
                float wy1 = py - y0f, wx1 = px - x0f;
                float wy0 = 1.f - wy1, wx0 = 1.f - wx1;
                bool yv0 = (y0 >= 0) && (y0 < Hh);
                bool yv1 = (y0 + 1 >= 0) && (y0 + 1 < Hh);
                bool xv0 = (x0 >= 0) && (x0 < Ww);
                bool xv1 = (x0 + 1 >= 0) && (x0 + 1 < Ww);
                float w00 = (yv0 && xv0) ? wy0 * wx0 * m : 0.f;
                float w01 = (yv0 && xv1) ? wy0 * wx1 * m : 0.f;
                float w10 = (yv1 && xv0) ? wy1 * wx0 * m : 0.f;
                float w11 = (yv1 && xv1) ? wy1 * wx1 * m : 0.f;
                int y0c = min(max(y0, 0), Hh - 1);
                int y1c = min(max(y0 + 1, 0), Hh - 1);
                int x0c = min(max(x0, 0), Ww - 1);
                int x1c = min(max(x0 + 1, 0), Ww - 1);
                wbuf[stid] = make_float4(w00, w01, w10, w11);
                ibuf[stid] = make_int4(y0c * Ww + x0c, y0c * Ww + x1c,
                                       y1c * Ww + x0c, y1c * Ww + x1c);
            }
            asm volatile("bar.sync 1, 256;" ::: "memory");

            // phase B: gather 32 pixels per warp, 2 per iteration
#pragma unroll 2
            for (int it = 0; it < 16; it++) {
                int p = wp * 32 + it * 2 + half;
                float4 w4 = wbuf[p];
                int4   i4 = ibuf[p];
                const float4* r00 = (const float4*)(xTb + (size_t)i4.x * Cc) + c4;
                const float4* r01 = (const float4*)(xTb + (size_t)i4.y * Cc) + c4;
                const float4* r10 = (const float4*)(xTb + (size_t)i4.z * Cc) + c4;
                const float4* r11 = (const float4*)(xTb + (size_t)i4.w * Cc) + c4;
                float4 v00 = __ldg(r00);
                float4 v01 = __ldg(r01);
                float4 v10 = __ldg(r10);
                float4 v11 = __ldg(r11);
                float4 s4;
                s4.x = w4.x * v00.x + w4.y * v01.x + w4.z * v10.x + w4.w * v11.x;
                s4.y = w4.x * v00.y + w4.y * v01.y + w4.z * v10.y + w4.w * v11.y;
                s4.z = w4.x * v00.z + w4.y * v01.z + w4.z * v10.z + w4.w * v11.z;
                s4.w = w4.x * v00.w + w4.y * v01.w + w4.z * v10.w + w4.w * v11.w;
                // swizzled STS: channel c = 4*c4+u, pixel p
                int gsw = ((p >> 1) ^ c4) * 2 + (p & 1);
                float* Sr = Sbuf + c4 * 4 * 256 + gsw;
                Sr[0]       = s4.x;
                Sr[256]     = s4.y;
                Sr[512]     = s4.z;
                Sr[768]     = s4.w;
            }

            MBARRIER_ARRIVE(sb + MB_FULL0 + s * 8);
        }
    } else {
        // ---------------- CONSUMER (GEMM) ----------------
        const int tx = tid & 63;                  // pixel group (4 pix each)
        const int ty = tid >> 6;                  // o group (16 o each)

        unsigned long long acc[16][2];
#pragma unroll
        for (int oi = 0; oi < 16; oi++) { acc[oi][0] = 0ull; acc[oi][1] = 0ull; }

        for (int k = 0; k < 9; k++) {
            const int s = k & 1;
            const int n = k >> 1;
            MBARRIER_WAIT_PARITY(sb + MB_FULL0 + s * 8, n & 1);

            const float4* Ws4 = (const float4*)(smc + BUF0 + s * BUFSZ);
            const unsigned long long* Sg =
                (const unsigned long long*)(smc + BUF0 + s * BUFSZ + 16384);

#pragma unroll 4
            for (int cc = 0; cc < 64; cc++) {
                int sw = cc >> 2;
                unsigned long long b0 = Sg[cc * 128 + ((2 * tx)     ^ sw)];
                unsigned long long b1 = Sg[cc * 128 + ((2 * tx + 1) ^ sw)];
#pragma unroll
                for (int g = 0; g < 4; g++) {
                    float4 av = Ws4[cc * 16 + ty * 4 + g];
                    unsigned long long a0 = pk2(av.x, av.x);
                    unsigned long long a1 = pk2(av.y, av.y);
                    unsigned long long a2 = pk2(av.z, av.z);
                    unsigned long long a3 = pk2(av.w, av.w);
                    fma2(acc[g * 4 + 0][0], a0, b0); fma2(acc[g * 4 + 0][1], a0, b1);
                    fma2(acc[g * 4 + 1][0], a1, b0); fma2(acc[g * 4 + 1][1], a1, b1);
                    fma2(acc[g * 4 + 2][0], a2, b0); fma2(acc[g * 4 + 2][1], a2, b1);
                    fma2(acc[g * 4 + 3][0], a3, b0); fma2(acc[g * 4 + 3][1], a3, b1);
                }
            }

            MBARRIER_ARRIVE(sb + MB_EMPT0 + s * 8);
        }

        // epilogue: 16 o rows x one float4 of pixels
        const int p0 = pbase + tx * 4;
        float* obp = out + (size_t)(b * 64 + ty * 16) * HWp + p0;
#pragma unroll
        for (int oi = 0; oi < 16; oi++) {
            float4 v;
            upk2(acc[oi][0], v.x, v.y);
            upk2(acc[oi][1], v.z, v.w);
            *(float4*)(obp + (size_t)oi * HWp) = v;
        }
    }
}

extern "C" void kernel_launch(void* const* d_in, const int* in_sizes, int n_in,
                              void* d_out, int out_size)
{
    const float* x        = (const float*)d_in[0];
    const float* offset_w = (const float*)d_in[1];
    const float* offset_b = (const float*)d_in[2];
    const float* mask_w   = (const float*)d_in[3];
    const float* mask_b   = (const float*)d_in[4];
    const float* dcn_w    = (const float*)d_in[5];
    float* out = (float*)d_out;

    const int smem1 = 64 * 9 * 28 * 4;      // 64512 B
    cudaFuncSetAttribute(omconv_kernel, cudaFuncAttributeMaxDynamicSharedMemorySize, smem1);
    cudaFuncSetAttribute(dcn_ws_kernel, cudaFuncAttributeMaxDynamicSharedMemorySize, SMEM_WS);

    xpose_kernel<<<dim3(800, 2, 4), dim3(32, 8)>>>(x);
    wpose_kernel<<<144, 256>>>(dcn_w);
    omconv_kernel<<<400, 128, smem1>>>(x, offset_w, offset_b, mask_w, mask_b);
    dcn_ws_kernel<<<400, 512, SMEM_WS>>>(out);
}